// round 9
// baseline (speedup 1.0000x reference)
#include <cuda_runtime.h>
#include <cuda_bf16.h>

// Problem constants (reference: B=32, A=4096, P=8388608, E=8)
#define Bn 32
#define An 4096
#define En 8

#define NBLK 16
#define PT 256
#define WPB (PT / 32)             // 8 warps/block
#define NW (NBLK * WPB)           // 128 warps
#define PREFIX (NW * 64)          // 8192 pairs in stage A (2 per lane)
#define WTILE 128                 // fallback tile (32 lanes x int4)

// Persistent device state. Zero at module load; the last-ticket block resets
// everything after the output is written, so each graph replay starts clean.
__device__ unsigned g_done;   // bit b => out[b]=1 (too_close OR eng_big)
__device__ unsigned g_ready;  // stage-A arrivals (one atomicAdd per warp)
__device__ unsigned g_count;  // completion ticket

__device__ __forceinline__ unsigned poll_u32(const unsigned* p) {
    unsigned v;
    asm volatile("ld.global.cg.u32 %0, [%1];" : "=r"(v) : "l"(p) : "memory");
    return v;
}

// One exact pair test; returns (1u<<n) if too close, else 0.
__device__ __forceinline__ unsigned pair_bit(const float* __restrict__ pos,
                                             const int* __restrict__ elm,
                                             const float* s_rad,
                                             int nb, int i, int j) {
    int ai = nb * An + i;
    int aj = nb * An + j;
    float ax = __ldg(pos + 3 * ai + 0);
    float ay = __ldg(pos + 3 * ai + 1);
    float az = __ldg(pos + 3 * ai + 2);
    float bx = __ldg(pos + 3 * aj + 0);
    float by = __ldg(pos + 3 * aj + 1);
    float bz = __ldg(pos + 3 * aj + 2);
    float rs = s_rad[__ldg(elm + ai)] + s_rad[__ldg(elm + aj)];
    float dx = bx - ax, dy = by - ay, dz = bz - az;
    float sod = dx * dx + dy * dy + dz * dz;
    return (rs * rs >= sod) ? (1u << nb) : 0u;
}

__global__ void __launch_bounds__(PT)
k_fused(const float* __restrict__ pos,
        const float* __restrict__ eng,
        const int* __restrict__ elm,
        const float* __restrict__ radius,
        const float* __restrict__ eng_atm,
        const int* __restrict__ nn,
        const int* __restrict__ ii,
        const int* __restrict__ jj,
        int P,
        float* __restrict__ out, int out_size) {
    __shared__ float s_rad[En];
    __shared__ unsigned s_mask;    // block-wide mask after rendezvous
    __shared__ unsigned s_ticket;

    const int tid  = threadIdx.x;
    const int bid  = blockIdx.x;
    const int wid  = tid >> 5;
    const int lane = tid & 31;
    const int gw   = bid * WPB + wid;

    if (tid < En) s_rad[tid] = radius[tid];
    __syncthreads();

    // ---- Stage A: two independent pairs per lane (overlapped latency).
    {
        int q = gw * 64 + lane * 2;
        unsigned local = 0u;
        if (q + 2 <= P) {
            int2 n2 = __ldg((const int2*)(nn + q));
            int2 i2 = __ldg((const int2*)(ii + q));
            int2 j2 = __ldg((const int2*)(jj + q));
            local  = pair_bit(pos, elm, s_rad, n2.x, i2.x, j2.x);
            local |= pair_bit(pos, elm, s_rad, n2.y, i2.y, j2.y);
        } else if (q < P) {
            local = pair_bit(pos, elm, s_rad, __ldg(nn + q), __ldg(ii + q),
                             __ldg(jj + q));
        }
        unsigned wbits = __reduce_or_sync(0xFFFFFFFFu, local);
        if (lane == 0) {
            if (wbits) atomicOr(&g_done, wbits);   // publish bits
            __threadfence();     // ORDER the OR before the ready-add
            atomicAdd(&g_ready, 1u);               // announce arrival
        }
    }

    // ---- Rendezvous: one poller per block (16 pollers, not 8192 threads).
    // All warps resident (single wave); every warp adds exactly once, so the
    // spin terminates. ready==NW now implies ALL mask bits are visible.
    if (tid == 0) {
        while (poll_u32(&g_ready) < NW) { }
        __threadfence();                           // acquire
        s_mask = poll_u32(&g_done);
    }
    __syncthreads();
    unsigned m = s_mask;

    if (m != 0xFFFFFFFFu) {
        // ---- Fallback 1 (normally skipped): scan remaining pairs [PREFIX,P).
        const long long ntiles = ((long long)P - PREFIX + WTILE - 1) / WTILE;
        for (long long t = gw; t < ntiles && m != 0xFFFFFFFFu; t += NW) {
            long long idx = (long long)PREFIX + t * WTILE + lane * 4;
            unsigned local = 0u;
            if (idx + 4 <= (long long)P) {
                int4 n4 = __ldg((const int4*)(nn + idx));
                int4 i4 = __ldg((const int4*)(ii + idx));
                int4 j4 = __ldg((const int4*)(jj + idx));
                int na[4] = {n4.x, n4.y, n4.z, n4.w};
                int ia[4] = {i4.x, i4.y, i4.z, i4.w};
                int ja[4] = {j4.x, j4.y, j4.z, j4.w};
                #pragma unroll
                for (int k = 0; k < 4; ++k)
                    if (!((m >> na[k]) & 1u))
                        local |= pair_bit(pos, elm, s_rad, na[k], ia[k], ja[k]);
            } else if (idx < (long long)P) {
                for (int k = 0; k < 4; ++k) {
                    long long q = idx + k;
                    if (q >= (long long)P) break;
                    int nb = __ldg(nn + q);
                    if (!((m >> nb) & 1u))
                        local |= pair_bit(pos, elm, s_rad, nb,
                                          __ldg(ii + q), __ldg(jj + q));
                }
            }
            unsigned wbits = __reduce_or_sync(0xFFFFFFFFu, local) & ~m;
            if (wbits && lane == 0) atomicOr(&g_done, wbits);
            m |= wbits | poll_u32(&g_done);
        }

        // ---- Fallback 2: eng_big for still-unflagged structures.
        // Warps 0..1 of block b handle structures 2b, 2b+1 (16 blocks x 2 = 32).
        if (wid < 2) {
            int sb = bid * 2 + wid;
            unsigned cur = poll_u32(&g_done);
            if (sb < Bn && !((cur >> sb) & 1u)) {
                float av = __ldg(eng_atm + (lane & (En - 1)));
                const int4* row = (const int4*)(elm + sb * An);
                float s = 0.f;
                #pragma unroll 4
                for (int t2 = lane; t2 < An / 4; t2 += 32) {
                    int4 e4 = __ldg(row + t2);
                    s += __shfl_sync(0xFFFFFFFFu, av, e4.x & 7);
                    s += __shfl_sync(0xFFFFFFFFu, av, e4.y & 7);
                    s += __shfl_sync(0xFFFFFFFFu, av, e4.z & 7);
                    s += __shfl_sync(0xFFFFFFFFu, av, e4.w & 7);
                }
                #pragma unroll
                for (int o = 16; o > 0; o >>= 1)
                    s += __shfl_down_sync(0xFFFFFFFFu, s, o);
                s = __shfl_sync(0xFFFFFFFFu, s, 0);
                if (lane == 0 && __ldg(eng + sb) >= s)
                    atomicOr(&g_done, 1u << sb);
            }
        }
    }

    // ---- Completion: last ticket block writes output, resets state.
    if (tid == 0) {
        __threadfence();                 // order fallback ORs before ticket
        s_ticket = atomicAdd(&g_count, 1u);
    }
    __syncthreads();

    if (s_ticket == (unsigned)(gridDim.x - 1)) {
        if (tid == 0) {
            __threadfence();             // acquire
            s_mask = atomicOr(&g_done, 0u);   // coherent final mask
        }
        __syncthreads();
        unsigned fm = s_mask;
        for (int b = tid; b < out_size; b += PT)
            out[b] = (b < Bn) ? (float)((fm >> b) & 1u) : 0.0f;
        __syncthreads();                 // writes done before reset
        if (tid == 0) { g_done = 0u; g_ready = 0u; g_count = 0u; }
    }
}

// ---------------------------------------------------------------------------
// Inputs (metadata order): pos[B,A,3] f32, eng[B] f32, elm[B,A] i32,
// radius[E] f32, eng_atm[E] f32, n[P] i32, i[P] i32, j[P] i32.
// Output: float32[B] (0.0 / 1.0).
extern "C" void kernel_launch(void* const* d_in, const int* in_sizes, int n_in,
                              void* d_out, int out_size) {
    const float* pos     = (const float*)d_in[0];
    const float* eng     = (const float*)d_in[1];
    const int*   elm     = (const int*)d_in[2];
    const float* radius  = (const float*)d_in[3];
    const float* eng_atm = (const float*)d_in[4];
    const int*   nn      = (const int*)d_in[5];
    const int*   ii      = (const int*)d_in[6];
    const int*   jj      = (const int*)d_in[7];
    int P = in_sizes[5];

    k_fused<<<NBLK, PT>>>(pos, eng, elm, radius, eng_atm, nn, ii, jj, P,
                          (float*)d_out, out_size);
}